// round 13
// baseline (speedup 1.0000x reference)
#include <cuda_runtime.h>
#include <cuda_fp16.h>
#include <cstdint>

// LorentzConv1d via single-pass fp16 mma.sync m16n8k16 (fp32 accum).
// Round 13: persistent warps (r12) + adjacency pair map -> A via LDS.64
// + epilogue t_resc from staged fp32 smem (no tail LDGs).
//
// K permutation (K=320, 20 kb x 8 pair-slots):
//   kb = 4*kIdx + jg (tap kIdx 0..4, channel-group jg 0..3)
//   pair w (0..7) of kb = (tap kIdx, channels 16jg + 4(w&3) + 2(w>>2) + {0,1})
//   channel 0 (time) slot multiplies B=0; t_resc is fp32 epilogue rank-1 term.
// A tile xq row-major fp16, word c = channels {2c,2c+1}, warp-private, XQS=40:
//   a0/a2 = LDS.64 at word q4*40 + kIdx*40 + 8jg + 2s4 (+16m*40); a1/a3 at +8 rows.
//   bank = 8*q4 + 2*s4 + const -> conflict-free per 16-lane phase.
// trw[36] per warp: fp32 time channel for exact t_resc in epilogue.

#define LLEN 8192
#define CIN  64
#define NSM  148
#define NWTOT (NSM * 16)              // 2368 warps
#define NTILES 4096                   // 16 batches x 256 tiles of 32 rows
#define XQS  40
#define TRW  (36 * XQS)               // fp32 time values, words 1440..1475
#define WPRIV 1480                    // 36*40 xq + 36 trw + 4 pad
#define WB4_OFF (16 * WPRIV)          // 23680 (16B aligned)
#define B_OFF   (WB4_OFF + 128)       // 23808 (16B aligned)
#define LGSTR   81                    // uint4 units per lane slot (20*4 + 1, odd)
#define B_UNITS (32 * LGSTR)          // 2592
#define SMEM_WORDS (B_OFF + B_UNITS * 4)  // 34176
#define SMEM_BYTES (SMEM_WORDS * 4)       // 136704

__device__ __forceinline__ uint32_t h2pack(float a, float b) {
    __half2 h = __floats2half2_rn(a, b);
    return *(uint32_t*)&h;
}
__device__ __forceinline__ void mma_f16(float* d, uint32_t a0, uint32_t a1,
                                        uint32_t a2, uint32_t a3,
                                        uint32_t b0, uint32_t b1) {
    asm volatile(
        "mma.sync.aligned.m16n8k16.row.col.f32.f16.f16.f32 "
        "{%0,%1,%2,%3}, {%4,%5,%6,%7}, {%8,%9}, {%0,%1,%2,%3};"
        : "+f"(d[0]), "+f"(d[1]), "+f"(d[2]), "+f"(d[3])
        : "r"(a0), "r"(a1), "r"(a2), "r"(a3), "r"(b0), "r"(b1));
}
// W weight for (kb, pair w, elem t): tap kIdx = kb>>2, ch = 16jg + 4(w&3) + 2(w>>2) + t
__device__ __forceinline__ float slotW(const float* __restrict__ W, int n,
                                       int kb, int w, int t) {
    int kIdx = kb >> 2;
    int jg   = kb & 3;
    int ch   = 16 * jg + 4 * (w & 3) + 2 * (w >> 2) + t;
    if (ch == 0) return 0.f;          // time channel: zero in GEMM
    return W[(size_t)n * 316 + (ch - 1) * 5 + kIdx + 1];
}

__global__ __launch_bounds__(512, 1)
void lorentz_f16_kernel(const float* __restrict__ x,
                        const float* __restrict__ W,
                        const float* __restrict__ bvec,
                        float* __restrict__ out)
{
    extern __shared__ uint32_t sm[];
    float4* wb4 = (float4*)(sm + WB4_OFF);
    uint4*  BQ4 = (uint4*)(sm + B_OFF);

    const int tid  = threadIdx.x;
    const int wid  = tid >> 5;
    const int lane = tid & 31;

    // ---- stage B (CTA-shared, once per SM): unit (lg, kb, i) ----
    for (int u = tid; u < 32 * 20 * 4; u += 512) {
        int i  = u & 3;
        int t2 = u >> 2;
        int kb = t2 % 20;
        int lg = t2 / 20;                      // 0..31
        int q4g = lg >> 2, s4g = lg & 3;
        int n0 = 16 * i + q4g;
        int n1 = n0 + 8;
        uint4 w;
        w.x = h2pack(slotW(W, n0, kb, s4g, 0),     slotW(W, n0, kb, s4g, 1));
        w.y = h2pack(slotW(W, n0, kb, s4g + 4, 0), slotW(W, n0, kb, s4g + 4, 1));
        w.z = h2pack(slotW(W, n1, kb, s4g, 0),     slotW(W, n1, kb, s4g, 1));
        w.w = h2pack(slotW(W, n1, kb, s4g + 4, 0), slotW(W, n1, kb, s4g + 4, 1));
        BQ4[lg * LGSTR + kb * 4 + i] = w;
    }
    // ---- fp32 time-weight + bias pairs ----
    if (tid < 32) {
        wb4[tid] = make_float4(W[(size_t)(2 * tid) * 316], bvec[2 * tid],
                               W[(size_t)(2 * tid + 1) * 316], bvec[2 * tid + 1]);
    }
    __syncthreads();   // the ONLY CTA-wide barrier

    const int q4 = lane >> 2;
    const int s4 = lane & 3;
    const int wpbase = wid * WPRIV;
    const int bx = wpbase + q4 * XQS + 2 * s4; // A base (word index)
    const int ub = (q4 * 4 + s4) * LGSTR;      // B base (uint4 index)
    const int gw = blockIdx.x * 16 + wid;      // global warp id
    float* trw = (float*)(sm + wpbase + TRW);

    // ---- persistent warp loop over 32-row tiles ----
    for (int t = gw; t < NTILES; t += NWTOT) {
        const int bidx = t >> 8;               // 256 tiles per batch
        const int l0   = (t & 255) << 5;
        const float* xb = x + (size_t)bidx * (LLEN * CIN);

        __syncwarp();   // previous tile's xq reads complete before overwrite

        // ---- warp-private xq staging: 36 rows (l0-2 .. l0+33) + fp32 time ----
        {
            const int gbase = l0 - 2;
#pragma unroll
            for (int j = 0; j < 18; j++) {
                int u  = j * 32 + lane;
                int r  = u >> 4, c4 = u & 15;
                int g  = gbase + r;
                float4 v;
                if ((unsigned)g < (unsigned)LLEN) v = *(const float4*)(xb + (size_t)g * CIN + c4 * 4);
                else { v = make_float4(0.f, 0.f, 0.f, 0.f); if (c4 == 0) v.x = 1.0f; }
                uint2 pw;
                pw.x = h2pack(v.x, v.y);
                pw.y = h2pack(v.z, v.w);
                *(uint2*)(sm + wpbase + r * XQS + c4 * 2) = pw;
                if (c4 == 0) trw[r] = v.x;     // exact fp32 time channel
            }
        }
        __syncwarp();

        // ---- mainloop: warp tile 32 rows x 64 cols, 20 k-blocks ----
        float d[2][8][4];
#pragma unroll
        for (int m = 0; m < 2; m++)
#pragma unroll
            for (int nb = 0; nb < 8; nb++)
                d[m][nb][0] = d[m][nb][1] = d[m][nb][2] = d[m][nb][3] = 0.f;

#pragma unroll
        for (int kb = 0; kb < 20; kb++) {
            const int kIdx = kb >> 2;
            const int jg   = kb & 3;
            const int boff = kIdx * XQS + 8 * jg;

            uint4 b0 = BQ4[ub + kb * 4 + 0];
            uint4 b1 = BQ4[ub + kb * 4 + 1];
            uint4 b2 = BQ4[ub + kb * 4 + 2];
            uint4 b3 = BQ4[ub + kb * 4 + 3];

#pragma unroll
            for (int m = 0; m < 2; m++) {
                const int base0 = bx + boff + (16 * m) * XQS;
                uint2 lo = *(const uint2*)(sm + base0);             // {a0, a2}
                uint2 hi = *(const uint2*)(sm + base0 + 8 * XQS);   // {a1, a3}
                mma_f16(d[m][0], lo.x, hi.x, lo.y, hi.y, b0.x, b0.y);
                mma_f16(d[m][1], lo.x, hi.x, lo.y, hi.y, b0.z, b0.w);
                mma_f16(d[m][2], lo.x, hi.x, lo.y, hi.y, b1.x, b1.y);
                mma_f16(d[m][3], lo.x, hi.x, lo.y, hi.y, b1.z, b1.w);
                mma_f16(d[m][4], lo.x, hi.x, lo.y, hi.y, b2.x, b2.y);
                mma_f16(d[m][5], lo.x, hi.x, lo.y, hi.y, b2.z, b2.w);
                mma_f16(d[m][6], lo.x, hi.x, lo.y, hi.y, b3.x, b3.y);
                mma_f16(d[m][7], lo.x, hi.x, lo.y, hi.y, b3.z, b3.w);
            }
        }

        // ---- epilogue: + W[:,0]*t_resc + b, Lorentz norm (in-warp over s4), store ----
#pragma unroll
        for (int m = 0; m < 2; m++) {
            const int ra = 16 * m + q4;
            float sa = -4.0f, sb = -4.0f;
#pragma unroll
            for (int k = 0; k < 5; k++) {
                float ta = trw[ra + k];        // row (l0+ra-2+k)
                float tb = trw[ra + 8 + k];
                sa = fmaf(ta, ta, sa);
                sb = fmaf(tb, tb, sb);
            }
            const float tra = sqrtf(sa);
            const float trb = sqrtf(sb);
            float ssa = 0.f, ssb = 0.f;
#pragma unroll
            for (int nb = 0; nb < 8; nb++) {
                float4 f4 = wb4[nb * 4 + s4];
                float y0 = fmaf(f4.x, tra, d[m][nb][0]) + f4.y;
                float y1 = fmaf(f4.z, tra, d[m][nb][1]) + f4.w;
                float y2 = fmaf(f4.x, trb, d[m][nb][2]) + f4.y;
                float y3 = fmaf(f4.z, trb, d[m][nb][3]) + f4.w;
                if (!(nb == 0 && s4 == 0)) {   // global col 0 excluded from the norm
                    ssa = fmaf(y0, y0, ssa);
                    ssb = fmaf(y2, y2, ssb);
                }
                ssa = fmaf(y1, y1, ssa);
                ssb = fmaf(y3, y3, ssb);
                d[m][nb][0] = y0; d[m][nb][1] = y1;
                d[m][nb][2] = y2; d[m][nb][3] = y3;
            }
            ssa += __shfl_xor_sync(0xffffffffu, ssa, 1);
            ssa += __shfl_xor_sync(0xffffffffu, ssa, 2);
            ssb += __shfl_xor_sync(0xffffffffu, ssb, 1);
            ssb += __shfl_xor_sync(0xffffffffu, ssb, 2);
            if (s4 == 0) {
                d[m][0][0] = sqrtf(ssa + 1.0f);
                d[m][0][2] = sqrtf(ssb + 1.0f);
            }

            const size_t oa = ((size_t)bidx * LLEN + (size_t)(l0 + ra)) * 64 + 2 * s4;
            const size_t ob = oa + 8 * 64;
#pragma unroll
            for (int nb = 0; nb < 8; nb++) {
                *(float2*)(out + oa + nb * 8) = make_float2(d[m][nb][0], d[m][nb][1]);
                *(float2*)(out + ob + nb * 8) = make_float2(d[m][nb][2], d[m][nb][3]);
            }
        }
    }
}

extern "C" void kernel_launch(void* const* d_in, const int* in_sizes, int n_in,
                              void* d_out, int out_size)
{
    const float* x = (const float*)d_in[0];
    const float* W = (const float*)d_in[1];
    const float* b = (const float*)d_in[2];
    float* out = (float*)d_out;

    cudaFuncSetAttribute(lorentz_f16_kernel,
                         cudaFuncAttributeMaxDynamicSharedMemorySize, SMEM_BYTES);
    lorentz_f16_kernel<<<NSM, 512, SMEM_BYTES>>>(x, W, b, out);
}

// round 14
// speedup vs baseline: 1.0801x; 1.0801x over previous
#include <cuda_runtime.h>
#include <cuda_fp16.h>
#include <cstdint>

// LorentzConv1d via single-pass fp16 mma.sync m16n8k16 (fp32 accum).
// Round 14: 448 threads (14 warps) -> 146-reg budget so ptxas can hoist
// loads ~2 kb deep. Structure otherwise identical to r13 (persistent warps,
// K=320 adjacency pair map, A via LDS.64, smem-fp32 t_resc epilogue).
//
// K permutation (K=320, 20 kb x 8 pair-slots):
//   kb = 4*kIdx + jg (tap kIdx 0..4, channel-group jg 0..3)
//   pair w (0..7) of kb = (tap kIdx, channels 16jg + 4(w&3) + 2(w>>2) + {0,1})
//   channel 0 (time) slot multiplies B=0; t_resc is fp32 epilogue rank-1 term.
// A tile xq row-major fp16, word c = channels {2c,2c+1}, warp-private, XQS=40.
// trw[36] per warp: fp32 time channel for exact t_resc in epilogue.

#define LLEN 8192
#define CIN  64
#define NSM  148
#define NW   14
#define NTHR (NW * 32)                // 448
#define NWTOT (NSM * NW)              // 2072 warps
#define NTILES 4096                   // 16 batches x 256 tiles of 32 rows
#define XQS  40
#define TRW  (36 * XQS)               // fp32 time values, words 1440..1475
#define WPRIV 1480                    // 36*40 xq + 36 trw + 4 pad
#define WB4_OFF (NW * WPRIV)          // 20720 (16B aligned)
#define B_OFF   (WB4_OFF + 128)       // 20848 (16B aligned)
#define LGSTR   81                    // uint4 units per lane slot (20*4 + 1, odd)
#define B_UNITS (32 * LGSTR)          // 2592
#define SMEM_WORDS (B_OFF + B_UNITS * 4)  // 31216
#define SMEM_BYTES (SMEM_WORDS * 4)       // 124864

__device__ __forceinline__ uint32_t h2pack(float a, float b) {
    __half2 h = __floats2half2_rn(a, b);
    return *(uint32_t*)&h;
}
__device__ __forceinline__ void mma_f16(float* d, uint32_t a0, uint32_t a1,
                                        uint32_t a2, uint32_t a3,
                                        uint32_t b0, uint32_t b1) {
    asm volatile(
        "mma.sync.aligned.m16n8k16.row.col.f32.f16.f16.f32 "
        "{%0,%1,%2,%3}, {%4,%5,%6,%7}, {%8,%9}, {%0,%1,%2,%3};"
        : "+f"(d[0]), "+f"(d[1]), "+f"(d[2]), "+f"(d[3])
        : "r"(a0), "r"(a1), "r"(a2), "r"(a3), "r"(b0), "r"(b1));
}
// W weight for (kb, pair w, elem t): tap kIdx = kb>>2, ch = 16jg + 4(w&3) + 2(w>>2) + t
__device__ __forceinline__ float slotW(const float* __restrict__ W, int n,
                                       int kb, int w, int t) {
    int kIdx = kb >> 2;
    int jg   = kb & 3;
    int ch   = 16 * jg + 4 * (w & 3) + 2 * (w >> 2) + t;
    if (ch == 0) return 0.f;          // time channel: zero in GEMM
    return W[(size_t)n * 316 + (ch - 1) * 5 + kIdx + 1];
}

__global__ __launch_bounds__(NTHR, 1)
void lorentz_f16_kernel(const float* __restrict__ x,
                        const float* __restrict__ W,
                        const float* __restrict__ bvec,
                        float* __restrict__ out)
{
    extern __shared__ uint32_t sm[];
    float4* wb4 = (float4*)(sm + WB4_OFF);
    uint4*  BQ4 = (uint4*)(sm + B_OFF);

    const int tid  = threadIdx.x;
    const int wid  = tid >> 5;
    const int lane = tid & 31;

    // ---- stage B (CTA-shared, once per SM): unit (lg, kb, i) ----
    for (int u = tid; u < 32 * 20 * 4; u += NTHR) {
        int i  = u & 3;
        int t2 = u >> 2;
        int kb = t2 % 20;
        int lg = t2 / 20;                      // 0..31
        int q4g = lg >> 2, s4g = lg & 3;
        int n0 = 16 * i + q4g;
        int n1 = n0 + 8;
        uint4 w;
        w.x = h2pack(slotW(W, n0, kb, s4g, 0),     slotW(W, n0, kb, s4g, 1));
        w.y = h2pack(slotW(W, n0, kb, s4g + 4, 0), slotW(W, n0, kb, s4g + 4, 1));
        w.z = h2pack(slotW(W, n1, kb, s4g, 0),     slotW(W, n1, kb, s4g, 1));
        w.w = h2pack(slotW(W, n1, kb, s4g + 4, 0), slotW(W, n1, kb, s4g + 4, 1));
        BQ4[lg * LGSTR + kb * 4 + i] = w;
    }
    // ---- fp32 time-weight + bias pairs ----
    if (tid < 32) {
        wb4[tid] = make_float4(W[(size_t)(2 * tid) * 316], bvec[2 * tid],
                               W[(size_t)(2 * tid + 1) * 316], bvec[2 * tid + 1]);
    }
    __syncthreads();   // the ONLY CTA-wide barrier

    const int q4 = lane >> 2;
    const int s4 = lane & 3;
    const int wpbase = wid * WPRIV;
    const int bx = wpbase + q4 * XQS + 2 * s4; // A base (word index)
    const int ub = (q4 * 4 + s4) * LGSTR;      // B base (uint4 index)
    const int gw = blockIdx.x * NW + wid;      // global warp id
    float* trw = (float*)(sm + wpbase + TRW);

    // ---- persistent warp loop over 32-row tiles ----
    for (int t = gw; t < NTILES; t += NWTOT) {
        const int bidx = t >> 8;               // 256 tiles per batch
        const int l0   = (t & 255) << 5;
        const float* xb = x + (size_t)bidx * (LLEN * CIN);

        __syncwarp();   // previous tile's xq reads complete before overwrite

        // ---- warp-private xq staging: 36 rows (l0-2 .. l0+33) + fp32 time ----
        {
            const int gbase = l0 - 2;
#pragma unroll
            for (int j = 0; j < 18; j++) {
                int u  = j * 32 + lane;
                int r  = u >> 4, c4 = u & 15;
                int g  = gbase + r;
                float4 v;
                if ((unsigned)g < (unsigned)LLEN) v = *(const float4*)(xb + (size_t)g * CIN + c4 * 4);
                else { v = make_float4(0.f, 0.f, 0.f, 0.f); if (c4 == 0) v.x = 1.0f; }
                uint2 pw;
                pw.x = h2pack(v.x, v.y);
                pw.y = h2pack(v.z, v.w);
                *(uint2*)(sm + wpbase + r * XQS + c4 * 2) = pw;
                if (c4 == 0) trw[r] = v.x;     // exact fp32 time channel
            }
        }
        __syncwarp();

        // ---- mainloop: warp tile 32 rows x 64 cols, 20 k-blocks ----
        float d[2][8][4];
#pragma unroll
        for (int m = 0; m < 2; m++)
#pragma unroll
            for (int nb = 0; nb < 8; nb++)
                d[m][nb][0] = d[m][nb][1] = d[m][nb][2] = d[m][nb][3] = 0.f;

#pragma unroll
        for (int kb = 0; kb < 20; kb++) {
            const int kIdx = kb >> 2;
            const int jg   = kb & 3;
            const int boff = kIdx * XQS + 8 * jg;

            uint4 b0 = BQ4[ub + kb * 4 + 0];
            uint4 b1 = BQ4[ub + kb * 4 + 1];
            uint4 b2 = BQ4[ub + kb * 4 + 2];
            uint4 b3 = BQ4[ub + kb * 4 + 3];

#pragma unroll
            for (int m = 0; m < 2; m++) {
                const int base0 = bx + boff + (16 * m) * XQS;
                uint2 lo = *(const uint2*)(sm + base0);             // {a0, a2}
                uint2 hi = *(const uint2*)(sm + base0 + 8 * XQS);   // {a1, a3}
                mma_f16(d[m][0], lo.x, hi.x, lo.y, hi.y, b0.x, b0.y);
                mma_f16(d[m][1], lo.x, hi.x, lo.y, hi.y, b0.z, b0.w);
                mma_f16(d[m][2], lo.x, hi.x, lo.y, hi.y, b1.x, b1.y);
                mma_f16(d[m][3], lo.x, hi.x, lo.y, hi.y, b1.z, b1.w);
                mma_f16(d[m][4], lo.x, hi.x, lo.y, hi.y, b2.x, b2.y);
                mma_f16(d[m][5], lo.x, hi.x, lo.y, hi.y, b2.z, b2.w);
                mma_f16(d[m][6], lo.x, hi.x, lo.y, hi.y, b3.x, b3.y);
                mma_f16(d[m][7], lo.x, hi.x, lo.y, hi.y, b3.z, b3.w);
            }
        }

        // ---- epilogue: + W[:,0]*t_resc + b, Lorentz norm (in-warp over s4), store ----
#pragma unroll
        for (int m = 0; m < 2; m++) {
            const int ra = 16 * m + q4;
            float sa = -4.0f, sb = -4.0f;
#pragma unroll
            for (int k = 0; k < 5; k++) {
                float ta = trw[ra + k];        // row (l0+ra-2+k)
                float tb = trw[ra + 8 + k];
                sa = fmaf(ta, ta, sa);
                sb = fmaf(tb, tb, sb);
            }
            const float tra = sqrtf(sa);
            const float trb = sqrtf(sb);
            float ssa = 0.f, ssb = 0.f;
#pragma unroll
            for (int nb = 0; nb < 8; nb++) {
                float4 f4 = wb4[nb * 4 + s4];
                float y0 = fmaf(f4.x, tra, d[m][nb][0]) + f4.y;
                float y1 = fmaf(f4.z, tra, d[m][nb][1]) + f4.w;
                float y2 = fmaf(f4.x, trb, d[m][nb][2]) + f4.y;
                float y3 = fmaf(f4.z, trb, d[m][nb][3]) + f4.w;
                if (!(nb == 0 && s4 == 0)) {   // global col 0 excluded from the norm
                    ssa = fmaf(y0, y0, ssa);
                    ssb = fmaf(y2, y2, ssb);
                }
                ssa = fmaf(y1, y1, ssa);
                ssb = fmaf(y3, y3, ssb);
                d[m][nb][0] = y0; d[m][nb][1] = y1;
                d[m][nb][2] = y2; d[m][nb][3] = y3;
            }
            ssa += __shfl_xor_sync(0xffffffffu, ssa, 1);
            ssa += __shfl_xor_sync(0xffffffffu, ssa, 2);
            ssb += __shfl_xor_sync(0xffffffffu, ssb, 1);
            ssb += __shfl_xor_sync(0xffffffffu, ssb, 2);
            if (s4 == 0) {
                d[m][0][0] = sqrtf(ssa + 1.0f);
                d[m][0][2] = sqrtf(ssb + 1.0f);
            }

            const size_t oa = ((size_t)bidx * LLEN + (size_t)(l0 + ra)) * 64 + 2 * s4;
            const size_t ob = oa + 8 * 64;
#pragma unroll
            for (int nb = 0; nb < 8; nb++) {
                *(float2*)(out + oa + nb * 8) = make_float2(d[m][nb][0], d[m][nb][1]);
                *(float2*)(out + ob + nb * 8) = make_float2(d[m][nb][2], d[m][nb][3]);
            }
        }
    }
}

extern "C" void kernel_launch(void* const* d_in, const int* in_sizes, int n_in,
                              void* d_out, int out_size)
{
    const float* x = (const float*)d_in[0];
    const float* W = (const float*)d_in[1];
    const float* b = (const float*)d_in[2];
    float* out = (float*)d_out;

    cudaFuncSetAttribute(lorentz_f16_kernel,
                         cudaFuncAttributeMaxDynamicSharedMemorySize, SMEM_BYTES);
    lorentz_f16_kernel<<<NSM, NTHR, SMEM_BYTES>>>(x, W, b, out);
}